// round 2
// baseline (speedup 1.0000x reference)
#include <cuda_runtime.h>

// NNSystem_mech: tiny neuro-endocrine ODE RHS.
// y: (2,1). Output: (2,1) float32.
// Input order (metadata):
// 0 t, 1 y, 2 aiw, 3 aib, 4 apw1, 5 apb1, 6 apw2, 7 apb2,
// 8 anw1, 9 anb1, 10 anw2, 11 anb2, 12 arw, 13 arb,
// 14 ciw, 15 cib, 16 cpw1, 17 cpb1, 18 cpw2, 19 cpb2,
// 20 cnw1, 21 cnb1, 22 cnw2, 23 cnb2, 24 crw, 25 crb, 26 K_i, 27 n_hill

struct Params {
    const float* y;
    const float* aiw; const float* aib;
    const float* apw1; const float* apb1; const float* apw2; const float* apb2;
    const float* anw1; const float* anb1; const float* anw2; const float* anb2;
    const float* arw; const float* arb;
    const float* ciw; const float* cib;
    const float* cpw1; const float* cpb1; const float* cpw2; const float* cpb2;
    const float* cnw1; const float* cnb1; const float* cnw2; const float* cnb2;
    const float* crw; const float* crb;
    const float* K_i; const float* n_hill;
};

__device__ __forceinline__ float softplusf(float x) {
    // jax.nn.softplus stable form: max(x,0) + log1p(exp(-|x|))
    return fmaxf(x, 0.0f) + log1pf(expf(-fabsf(x)));
}

__global__ void nnsys_kernel(Params p, float* out) {
    __shared__ float partial[40];
    const int tid = threadIdx.x;

    const float y0 = p.y[0];
    const float y1 = p.y[1];

    if (tid < 40) {
        const int g = tid / 10;   // which MLP: 0=a_pos, 1=a_neg, 2=c_pos, 3=c_neg
        const int u = tid % 10;   // hidden unit

        float x, w1, b1, w2;
        if (g == 0) {
            x  = softplusf(p.aiw[0] * y0 + p.aib[0]);
            w1 = p.apw1[u]; b1 = p.apb1[u]; w2 = p.apw2[u];
        } else if (g == 1) {
            x  = softplusf(p.aiw[1] * y0 + p.aib[1]);
            w1 = p.anw1[u]; b1 = p.anb1[u]; w2 = p.anw2[u];
        } else if (g == 2) {
            x  = softplusf(p.ciw[0] * y1 + p.cib[0]);
            w1 = p.cpw1[u]; b1 = p.cpb1[u]; w2 = p.cpw2[u];
        } else {
            x  = softplusf(p.ciw[1] * y1 + p.cib[1]);
            w1 = p.cnw1[u]; b1 = p.cnb1[u]; w2 = p.cnw2[u];
        }
        partial[tid] = w2 * softplusf(fmaf(w1, x, b1));
    }
    __syncthreads();

    if (tid == 0) {
        float s0 = 0.f, s1 = 0.f, s2 = 0.f, s3 = 0.f;
        #pragma unroll
        for (int u = 0; u < 10; u++) {
            s0 += partial[u];
            s1 += partial[10 + u];
            s2 += partial[20 + u];
            s3 += partial[30 + u];
        }
        const float a_pos = s0 + p.apb2[0];
        const float a_neg = s1 + p.anb2[0];
        const float c_pos = s2 + p.cpb2[0];
        const float c_neg = s3 + p.cnb2[0];

        const float n  = p.n_hill[0];
        const float Kn = powf(p.K_i[0], n);
        const float hill = Kn / (Kn + powf(y1, n));

        const float av0 = softplusf(hill * a_pos);
        const float av1 = softplusf(a_neg);
        const float dy_acth = fmaf(p.arw[0], av0, fmaf(p.arw[1], av1, p.arb[0]));

        const float cv0 = softplusf(y0 * c_pos);
        const float cv1 = softplusf(c_neg);
        const float dy_cort = fmaf(p.crw[0], cv0, fmaf(p.crw[1], cv1, p.crb[0]));

        out[0] = dy_acth;
        out[1] = dy_cort;
    }
}

extern "C" void kernel_launch(void* const* d_in, const int* in_sizes, int n_in,
                              void* d_out, int out_size) {
    (void)in_sizes; (void)n_in; (void)out_size;
    Params p;
    p.y    = (const float*)d_in[1];
    p.aiw  = (const float*)d_in[2];  p.aib  = (const float*)d_in[3];
    p.apw1 = (const float*)d_in[4];  p.apb1 = (const float*)d_in[5];
    p.apw2 = (const float*)d_in[6];  p.apb2 = (const float*)d_in[7];
    p.anw1 = (const float*)d_in[8];  p.anb1 = (const float*)d_in[9];
    p.anw2 = (const float*)d_in[10]; p.anb2 = (const float*)d_in[11];
    p.arw  = (const float*)d_in[12]; p.arb  = (const float*)d_in[13];
    p.ciw  = (const float*)d_in[14]; p.cib  = (const float*)d_in[15];
    p.cpw1 = (const float*)d_in[16]; p.cpb1 = (const float*)d_in[17];
    p.cpw2 = (const float*)d_in[18]; p.cpb2 = (const float*)d_in[19];
    p.cnw1 = (const float*)d_in[20]; p.cnb1 = (const float*)d_in[21];
    p.cnw2 = (const float*)d_in[22]; p.cnb2 = (const float*)d_in[23];
    p.crw  = (const float*)d_in[24]; p.crb  = (const float*)d_in[25];
    p.K_i  = (const float*)d_in[26]; p.n_hill = (const float*)d_in[27];

    nnsys_kernel<<<1, 64>>>(p, (float*)d_out);
}